// round 2
// baseline (speedup 1.0000x reference)
#include <cuda_runtime.h>
#include <stdint.h>

// Shapes (fixed for this problem)
#define T_    4
#define B_    64
#define C_    384
#define N_    196
#define NH_   8
#define D_    48
#define BNN   (B_*N_)      // 12544
#define TBN   (T_*BNN)     // 50176
#define CN    (C_*N_)      // 75264
#define BCN   (B_*CN)      // 4816896
#define TBCN  (T_*BCN)     // 19267584

// ---------------- device scratch (static; no runtime allocation) ----------------
__device__ uint8_t g_xs[(size_t)C_*TBN];        // input spikes,  layout [c][t][b][n]
__device__ float   g_y [(size_t)3*C_*TBN];      // BN'd q/k/v pre-LIF, [br][c][t][b][n]
__device__ uint8_t g_s [(size_t)3*C_*TBN];      // q/k/v spikes
__device__ float   g_ya[(size_t)C_*TBN];        // attention output pre-LIF
__device__ uint8_t g_sa[(size_t)C_*TBN];        // attn spikes

// ---------------- LIF kernels (replicate reference fp32 op order exactly) -------
__global__ void k_lif_in(const float* __restrict__ x)
{
    int i = blockIdx.x*blockDim.x + threadIdx.x;
    if (i >= BCN) return;
    int b = i / CN; int r = i - b*CN; int c = r / N_; int n = r - c*N_;
    size_t dst = (size_t)c*TBN + (size_t)b*N_ + n;
    float v = 0.0f;
    #pragma unroll
    for (int t = 0; t < T_; t++) {
        float xv = x[(size_t)t*BCN + i];
        v = __fadd_rn(v, __fmul_rn(__fsub_rn(xv, v), 0.5f));   // v += (x - v)/2
        uint8_t s = (v >= 1.0f);
        if (s) v = 0.0f;
        g_xs[dst + (size_t)t*BNN] = s;
    }
}

__global__ void k_lif_qkv()
{
    size_t i = (size_t)blockIdx.x*blockDim.x + threadIdx.x;
    if (i >= (size_t)3*C_*BNN) return;
    size_t row = i / BNN; size_t j = i - row*BNN;
    const float* yp = g_y + row*TBN + j;
    uint8_t*     sp = g_s + row*TBN + j;
    float v = 0.0f;
    #pragma unroll
    for (int t = 0; t < T_; t++) {
        v = __fadd_rn(v, __fmul_rn(__fsub_rn(yp[(size_t)t*BNN], v), 0.5f));
        uint8_t s = (v >= 1.0f);
        if (s) v = 0.0f;
        sp[(size_t)t*BNN] = s;
    }
}

__global__ void k_lif_attn()
{
    size_t i = (size_t)blockIdx.x*blockDim.x + threadIdx.x;
    if (i >= (size_t)C_*BNN) return;
    size_t row = i / BNN; size_t j = i - row*BNN;
    const float* yp = g_ya + row*TBN + j;
    uint8_t*     sp = g_sa + row*TBN + j;
    float v = 0.0f;
    #pragma unroll
    for (int t = 0; t < T_; t++) {
        v = __fadd_rn(v, __fmul_rn(__fsub_rn(yp[(size_t)t*BNN], v), 0.5f));
        uint8_t s = (v >= 0.5f);
        if (s) v = 0.0f;
        sp[(size_t)t*BNN] = s;
    }
}

// ---------------- fp32 GEMM core: Y[128x128 tile] = W[M,K] * X[K, TBN] ----------
// A fp32 row-major (lda=384), B uint8 spikes (ldb=TBN). 256 threads, 8x8 per thread.
__device__ __forceinline__ void gemm_acc(
    const float* __restrict__ A, const uint8_t* __restrict__ Bx,
    int m0, int n0, float (&acc)[8][8],
    float (*As)[36], float (*Bs)[128])
{
    int tid = threadIdx.x;
    int tx = tid & 15, ty = tid >> 4;
    for (int k0 = 0; k0 < C_; k0 += 32) {
        #pragma unroll
        for (int i = 0; i < 4; i++) {
            int idx = tid + i*256; int row = idx >> 3; int c4 = idx & 7;
            float4 v = *(const float4*)(A + (size_t)(m0+row)*C_ + k0 + c4*4);
            *(float4*)&As[row][c4*4] = v;
        }
        #pragma unroll
        for (int i = 0; i < 4; i++) {
            int idx = tid + i*256; int row = idx >> 5; int c4 = idx & 31;
            uchar4 u = *(const uchar4*)(Bx + (size_t)(k0+row)*TBN + n0 + c4*4);
            Bs[row][c4*4+0] = (float)u.x; Bs[row][c4*4+1] = (float)u.y;
            Bs[row][c4*4+2] = (float)u.z; Bs[row][c4*4+3] = (float)u.w;
        }
        __syncthreads();
        #pragma unroll
        for (int k = 0; k < 32; k++) {
            float a[8], b[8];
            #pragma unroll
            for (int i = 0; i < 8; i++) a[i] = As[ty*8+i][k];
            float4 b0 = *(const float4*)&Bs[k][tx*8];
            float4 b1 = *(const float4*)&Bs[k][tx*8+4];
            b[0]=b0.x; b[1]=b0.y; b[2]=b0.z; b[3]=b0.w;
            b[4]=b1.x; b[5]=b1.y; b[6]=b1.z; b[7]=b1.w;
            #pragma unroll
            for (int i = 0; i < 8; i++)
                #pragma unroll
                for (int j = 0; j < 8; j++)
                    acc[i][j] += a[i]*b[j];
        }
        __syncthreads();
    }
}

// q/k/v projection + BN epilogue. grid = (392, 3, 3[branch])
__global__ __launch_bounds__(256) void k_gemm_qkv(
    const float* __restrict__ Wq, const float* __restrict__ Wk, const float* __restrict__ Wv,
    const float* __restrict__ Pq, const float* __restrict__ Pk, const float* __restrict__ Pv)
{
    __shared__ float As[128][36];
    __shared__ float Bs[32][128];
    int br = blockIdx.z;
    const float* A = (br==0) ? Wq : ((br==1) ? Wk : Wv);
    const float* P = (br==0) ? Pq : ((br==1) ? Pk : Pv);
    float* Yo = g_y + (size_t)br*C_*TBN;
    int m0 = blockIdx.y*128, n0 = blockIdx.x*128;
    float acc[8][8];
    #pragma unroll
    for (int i = 0; i < 8; i++)
        #pragma unroll
        for (int j = 0; j < 8; j++) acc[i][j] = 0.0f;
    gemm_acc(A, g_xs, m0, n0, acc, As, Bs);
    int tx = threadIdx.x & 15, ty = threadIdx.x >> 4;
    #pragma unroll
    for (int i = 0; i < 8; i++) {
        int d = m0 + ty*8 + i;
        float g  = P[d], be = P[C_+d], mn = P[2*C_+d], va = P[3*C_+d];
        float inv = g / sqrtf(va + 1e-5f);
        float ad  = be - mn*inv;
        float* yr = Yo + (size_t)d*TBN + n0 + tx*8;
        #pragma unroll
        for (int j = 0; j < 8; j++) yr[j] = acc[i][j]*inv + ad;
    }
}

// proj GEMM + bias + BN + identity add; writes final output. grid = (392, 3)
__global__ __launch_bounds__(256) void k_gemm_proj(
    const float* __restrict__ W, const float* __restrict__ bias,
    const float* __restrict__ P, const float* __restrict__ x,
    float* __restrict__ out)
{
    __shared__ float As[128][36];
    __shared__ float Bs[32][128];
    int m0 = blockIdx.y*128, n0 = blockIdx.x*128;
    float acc[8][8];
    #pragma unroll
    for (int i = 0; i < 8; i++)
        #pragma unroll
        for (int j = 0; j < 8; j++) acc[i][j] = 0.0f;
    gemm_acc(W, g_sa, m0, n0, acc, As, Bs);
    int tx = threadIdx.x & 15, ty = threadIdx.x >> 4;
    #pragma unroll
    for (int i = 0; i < 8; i++) {
        int d = m0 + ty*8 + i;
        float g  = P[d], be = P[C_+d], mn = P[2*C_+d], va = P[3*C_+d];
        float inv = g / sqrtf(va + 1e-5f);
        float ad  = be - mn*inv;
        float bb  = bias[d];
        #pragma unroll
        for (int j = 0; j < 8; j++) {
            int col = n0 + tx*8 + j;
            int t = col / BNN; int r = col - t*BNN; int b = r / N_; int n = r - b*N_;
            size_t oi = (size_t)t*BCN + (size_t)b*CN + (size_t)d*N_ + n;
            out[oi] = (acc[i][j] + bb)*inv + ad + x[oi];
        }
    }
}

// ---------------- attention: y = q @ (k^T v), all-integer (exact) ---------------
// grid = T*B*NH = 2048 blocks, 256 threads. Bitpacked 48-bit spike rows.
__global__ __launch_bounds__(256) void k_attn()
{
    __shared__ uint8_t tile[48][200];
    __shared__ unsigned long long qp[196];
    __shared__ unsigned long long km[48][4];
    __shared__ unsigned long long vm[48][4];
    __shared__ int kv[48][49];              // stride 49 -> conflict-free phase-3 reads

    int tid = threadIdx.x;
    int blk = blockIdx.x;
    int h = blk & 7; int tb = blk >> 3; int b = tb & 63; int t = tb >> 6;
    size_t jbase = (size_t)t*BNN + (size_t)b*N_;
    const uint8_t* qbp = g_s + (size_t)(h*D_)*TBN + jbase;
    const uint8_t* kbp = qbp + (size_t)C_*TBN;
    const uint8_t* vbp = kbp + (size_t)C_*TBN;

    // zero tile pad cols [196,200) once (k/v packing reads past 196)
    if (tid < 48) { tile[tid][196]=0; tile[tid][197]=0; tile[tid][198]=0; tile[tid][199]=0; }

    // ---- K tile -> km ----
    for (int i = tid; i < 48*49; i += 256) {
        int c = i/49, g4 = i - c*49;
        *(uchar4*)&tile[c][g4*4] = *(const uchar4*)(kbp + (size_t)c*TBN + g4*4);
    }
    __syncthreads();
    if (tid < 192) {
        int c = tid >> 2, w = tid & 3;
        const unsigned long long* rw = (const unsigned long long*)&tile[c][0];
        unsigned long long bits;
        if (w < 3) {
            bits = 0ULL;
            #pragma unroll
            for (int jj = 0; jj < 8; jj++)
                bits |= ((rw[w*8+jj] * 0x0102040810204080ULL) >> 56) << (8*jj);
        } else {
            bits = ((rw[24] * 0x0102040810204080ULL) >> 56) & 0xFULL;  // m = 192..195
        }
        km[c][w] = bits;
    }
    __syncthreads();

    // ---- V tile -> vm ----
    for (int i = tid; i < 48*49; i += 256) {
        int c = i/49, g4 = i - c*49;
        *(uchar4*)&tile[c][g4*4] = *(const uchar4*)(vbp + (size_t)c*TBN + g4*4);
    }
    __syncthreads();
    if (tid < 192) {
        int c = tid >> 2, w = tid & 3;
        const unsigned long long* rw = (const unsigned long long*)&tile[c][0];
        unsigned long long bits;
        if (w < 3) {
            bits = 0ULL;
            #pragma unroll
            for (int jj = 0; jj < 8; jj++)
                bits |= ((rw[w*8+jj] * 0x0102040810204080ULL) >> 56) << (8*jj);
        } else {
            bits = ((rw[24] * 0x0102040810204080ULL) >> 56) & 0xFULL;
        }
        vm[c][w] = bits;
    }
    __syncthreads();

    // ---- Q tile ----
    for (int i = tid; i < 48*49; i += 256) {
        int c = i/49, g4 = i - c*49;
        *(uchar4*)&tile[c][g4*4] = *(const uchar4*)(qbp + (size_t)c*TBN + g4*4);
    }
    __syncthreads();

    // qp (tid<196) and kv = k^T v via popcount (all threads)
    if (tid < 196) {
        unsigned long long q = 0ULL;
        #pragma unroll
        for (int dd = 0; dd < 48; dd++)
            q |= ((unsigned long long)tile[dd][tid]) << dd;
        qp[tid] = q;
    }
    for (int i = tid; i < 48*48; i += 256) {
        int cc = i/48, d2 = i - cc*48;
        int s = 0;
        #pragma unroll
        for (int w = 0; w < 4; w++) s += __popcll(km[cc][w] & vm[d2][w]);
        kv[cc][d2] = s;
    }
    __syncthreads();

    // y[n, dd] = sum over set bits c of qp[n] of kv[c][dd]; scaled by 0.125
    if (tid < 196) {
        int y[48];
        #pragma unroll
        for (int dd = 0; dd < 48; dd++) y[dd] = 0;
        unsigned long long m = qp[tid];
        while (m) {
            int c = __ffsll((long long)m) - 1;
            m &= m - 1;
            const int* row = kv[c];
            #pragma unroll
            for (int dd = 0; dd < 48; dd++) y[dd] += row[dd];
        }
        float* ob = g_ya + (size_t)(h*D_)*TBN + jbase + tid;
        #pragma unroll
        for (int dd = 0; dd < 48; dd++)
            ob[(size_t)dd*TBN] = (float)y[dd] * 0.125f;
    }
}

// ---------------- launch --------------------------------------------------------
extern "C" void kernel_launch(void* const* d_in, const int* in_sizes, int n_in,
                              void* d_out, int out_size)
{
    const float* x   = (const float*)d_in[0];
    const float* qw  = (const float*)d_in[1];
    const float* kw  = (const float*)d_in[2];
    const float* vw  = (const float*)d_in[3];
    const float* pw  = (const float*)d_in[4];
    const float* pb  = (const float*)d_in[5];
    const float* qbn = (const float*)d_in[6];
    const float* kbn = (const float*)d_in[7];
    const float* vbn = (const float*)d_in[8];
    const float* pbn = (const float*)d_in[9];
    float* out = (float*)d_out;

    k_lif_in<<<(BCN + 255)/256, 256>>>(x);
    k_gemm_qkv<<<dim3(TBN/128, C_/128, 3), 256>>>(qw, kw, vw, qbn, kbn, vbn);
    k_lif_qkv<<<(3*C_*BNN + 255)/256, 256>>>();
    k_attn<<<T_*B_*NH_, 256>>>();
    k_lif_attn<<<(C_*BNN + 255)/256, 256>>>();
    k_gemm_proj<<<dim3(TBN/128, C_/128), 256>>>(pw, pb, pbn, x, out);
}

// round 6
// speedup vs baseline: 1.8490x; 1.8490x over previous
#include <cuda_runtime.h>
#include <cuda_bf16.h>
#include <stdint.h>

#define T_    4
#define B_    64
#define C_    384
#define N_    196
#define BNN   12544
#define TBN   50176
#define CN    75264
#define BCN   4816896
#define WSZ   147456

// GEMM tiling
#define KC            32
#define A_SPLIT_BYTES 10240              // 128 rows * 80B
#define A_STAGE       (3*A_SPLIT_BYTES)  // 30720
#define B_STAGE       20480              // 256 rows * 80B
#define STAGE_B       (A_STAGE + B_STAGE)// 51200
#define SMEM_DYN      (2*STAGE_B)        // 102400

// ---------------- device scratch ----------------
__device__ unsigned short g_w3 [(size_t)4*3*WSZ];   // bf16 W splits [br][split][d][c]
__device__ unsigned short g_xsT[(size_t)TBN*C_];    // input spikes bf16 [j][c]
__device__ unsigned short g_sq [(size_t)TBN*C_];
__device__ unsigned short g_sk [(size_t)TBN*C_];
__device__ unsigned short g_sv [(size_t)TBN*C_];
__device__ unsigned short g_sa [(size_t)TBN*C_];
__device__ float          g_ya [(size_t)TBN*C_];    // attn out fp32 [j][c]

// ---------------- PTX helpers (sm_100-baseline safe) ----------------
__device__ __forceinline__ uint32_t smem_u32(const void* p) {
    uint32_t a;
    asm("{ .reg .u64 t; cvta.to.shared.u64 t, %1; cvt.u32.u64 %0, t; }" : "=r"(a) : "l"(p));
    return a;
}
#define CP_ASYNC16(dst, src) \
    asm volatile("cp.async.cg.shared.global [%0], [%1], 16;" :: "r"(dst), "l"(src))
#define CP_COMMIT() asm volatile("cp.async.commit_group;" ::: "memory")
#define CP_WAIT1()  asm volatile("cp.async.wait_group 1;" ::: "memory")
#define CP_WAIT0()  asm volatile("cp.async.wait_group 0;" ::: "memory")
#define LDSM4(r0, r1, r2, r3, addr) \
    asm volatile("ldmatrix.sync.aligned.m8n8.x4.shared.b16 {%0,%1,%2,%3}, [%4];" \
        : "=r"(r0), "=r"(r1), "=r"(r2), "=r"(r3) : "r"(addr))
#define MMA16816(d, a, b) \
    asm volatile("mma.sync.aligned.m16n8k16.row.col.f32.bf16.bf16.f32 " \
        "{%0,%1,%2,%3},{%4,%5,%6,%7},{%8,%9},{%0,%1,%2,%3};" \
        : "+f"((d)[0]), "+f"((d)[1]), "+f"((d)[2]), "+f"((d)[3]) \
        : "r"((a)[0]), "r"((a)[1]), "r"((a)[2]), "r"((a)[3]), "r"((b)[0]), "r"((b)[1]))

// ---------------- W split: fp32 -> 3x bf16 ----------------
__global__ void k_wsplit(const float* __restrict__ qw, const float* __restrict__ kw,
                         const float* __restrict__ vw, const float* __restrict__ pw)
{
    int i = blockIdx.x*256 + threadIdx.x;
    if (i >= WSZ) return;
    const float* Ws[4] = {qw, kw, vw, pw};
    #pragma unroll
    for (int br = 0; br < 4; br++) {
        float w = Ws[br][i];
        __nv_bfloat16 h = __float2bfloat16(w);
        float r1 = w - __bfloat162float(h);
        __nv_bfloat16 m = __float2bfloat16(r1);
        float r2 = r1 - __bfloat162float(m);
        __nv_bfloat16 l = __float2bfloat16(r2);
        g_w3[((size_t)(br*3+0))*WSZ + i] = *(unsigned short*)&h;
        g_w3[((size_t)(br*3+1))*WSZ + i] = *(unsigned short*)&m;
        g_w3[((size_t)(br*3+2))*WSZ + i] = *(unsigned short*)&l;
    }
}

// ---------------- input LIF -> transposed bf16 spikes [j][c] --------------------
__global__ void k_lif_in(const float* __restrict__ x)
{
    __shared__ unsigned short sm[4][32][40];
    int nx = threadIdx.x, ty = threadIdx.y;
    int b = blockIdx.z, c0 = blockIdx.y*32, n0 = blockIdx.x*32;
    int n = n0 + nx;
    if (n < N_) {
        #pragma unroll
        for (int kk = 0; kk < 4; kk++) {
            int cl = ty*4 + kk;
            const float* xp = x + (size_t)b*CN + (size_t)(c0+cl)*N_ + n;
            float v = 0.f;
            #pragma unroll
            for (int t = 0; t < T_; t++) {
                float xv = xp[(size_t)t*BCN];
                v = __fadd_rn(v, __fmul_rn(__fsub_rn(xv, v), 0.5f));
                unsigned short s = 0;
                if (v >= 1.0f) { s = 0x3F80; v = 0.f; }
                sm[t][nx][cl] = s;
            }
        }
    }
    __syncthreads();
    int tid = ty*32 + nx;
    #pragma unroll
    for (int it = 0; it < 2; it++) {
        int task = tid + it*256;
        int row = task >> 2, q = task & 3;
        int t = row >> 5, nl = row & 31;
        if (n0 + nl < N_) {
            uint4 val = *(uint4*)&sm[t][nl][q*8];
            size_t j = (size_t)t*BNN + (size_t)b*N_ + n0 + nl;
            *(uint4*)((char*)g_xsT + j*768 + (size_t)(c0 + q*8)*2) = val;
        }
    }
}

// ---------------- attention LIF: g_ya -> g_sa (thr 0.5) -------------------------
__global__ void k_lif_attn()
{
    size_t i = (size_t)blockIdx.x*256 + threadIdx.x;
    if (i >= (size_t)BNN*C_) return;
    const float* yp = g_ya + i;
    unsigned short* sp = g_sa + i;
    float v = 0.f;
    #pragma unroll
    for (int t = 0; t < T_; t++) {
        v = __fadd_rn(v, __fmul_rn(__fsub_rn(yp[(size_t)t*BNN*C_], v), 0.5f));
        unsigned short s = 0;
        if (v >= 0.5f) { s = 0x3F80; v = 0.f; }
        sp[(size_t)t*BNN*C_] = s;
    }
}

// ---------------- cp.async chunk loader ----------------
__device__ __forceinline__ void gemm_load_chunk(
    const unsigned short* __restrict__ Asrc, const unsigned short* __restrict__ Bsrc,
    int m0, int bn0, int kc, char* stagep, int tid)
{
    char* Ab = stagep;
    char* Bb = stagep + A_STAGE;
    #pragma unroll
    for (int i = 0; i < 6; i++) {                 // A: 3 splits x 128 rows x 64B
        int u = tid + i*256;
        int s = u >> 9, r = (u >> 2) & 127, q = u & 3;
        const unsigned short* src = Asrc + (size_t)s*WSZ + (size_t)(m0+r)*C_ + kc*KC + q*8;
        uint32_t dst = smem_u32(Ab + s*A_SPLIT_BYTES + r*80 + q*16);
        CP_ASYNC16(dst, (const void*)src);
    }
    #pragma unroll
    for (int i = 0; i < 4; i++) {                 // B: 256 rows x 64B
        int u = tid + i*256;
        int r = u >> 2, q = u & 3;
        int j = (r >> 6)*BNN + bn0 + (r & 63);
        const unsigned short* src = Bsrc + (size_t)j*C_ + kc*KC + q*8;
        uint32_t dst = smem_u32(Bb + r*80 + q*16);
        CP_ASYNC16(dst, (const void*)src);
    }
    CP_COMMIT();
}

// ---------------- mma.sync GEMM: D[128,256] = sum_s W_s[128x384] @ S^T ----------
// mode 0: qkv (br=blockIdx.z, B=g_xsT, epilogue BN+LIF -> spikes)
// mode 1: proj (br=3, B=g_sa, epilogue bias+BN+identity -> out)
__global__ __launch_bounds__(256) void k_gemm(
    int mode,
    const float* __restrict__ bnq, const float* __restrict__ bnk,
    const float* __restrict__ bnv, const float* __restrict__ bnp,
    const float* __restrict__ bias,
    const float* __restrict__ x, float* __restrict__ out)
{
    extern __shared__ __align__(128) char smem[];
    int tid = threadIdx.x, wid = tid >> 5, lane = tid & 31;
    int wm = wid >> 2, wn = wid & 3;              // warp grid 2(M) x 4(N), tile 64x64
    int br = (mode == 0) ? blockIdx.z : 3;
    int m0 = blockIdx.y*128;
    int bn0 = blockIdx.x*64;
    const unsigned short* Bsrc = (mode == 0) ? g_xsT : g_sa;
    const unsigned short* Asrc = g_w3 + (size_t)br*3*WSZ;

    float acc[4][8][4];
    #pragma unroll
    for (int i = 0; i < 4; i++)
        #pragma unroll
        for (int j = 0; j < 8; j++)
            #pragma unroll
            for (int k = 0; k < 4; k++) acc[i][j][k] = 0.f;

    gemm_load_chunk(Asrc, Bsrc, m0, bn0, 0, smem, tid);

    for (int kc = 0; kc < 12; kc++) {
        if (kc < 11) {
            gemm_load_chunk(Asrc, Bsrc, m0, bn0, kc+1, smem + ((kc+1)&1)*STAGE_B, tid);
            CP_WAIT1();
        } else {
            CP_WAIT0();
        }
        __syncthreads();
        uint32_t Ab = smem_u32(smem + (kc&1)*STAGE_B);
        uint32_t Bb = Ab + A_STAGE;
        #pragma unroll
        for (int ks = 0; ks < 2; ks++) {
            uint32_t bfr[8][2];
            #pragma unroll
            for (int nf2 = 0; nf2 < 4; nf2++) {
                uint32_t addr = Bb + (uint32_t)((wn*64 + nf2*16 + ((lane>>4)<<3) + (lane&7))*80
                                                + (ks*16 + ((lane>>3)&1)*8)*2);
                LDSM4(bfr[nf2*2][0], bfr[nf2*2][1], bfr[nf2*2+1][0], bfr[nf2*2+1][1], addr);
            }
            #pragma unroll
            for (int s = 0; s < 3; s++) {
                uint32_t afr[4][4];
                #pragma unroll
                for (int mf = 0; mf < 4; mf++) {
                    uint32_t addr = Ab + (uint32_t)(s*A_SPLIT_BYTES
                                    + (wm*64 + mf*16 + (lane&15))*80
                                    + (ks*16 + (lane>>4)*8)*2);
                    LDSM4(afr[mf][0], afr[mf][1], afr[mf][2], afr[mf][3], addr);
                }
                #pragma unroll
                for (int mf = 0; mf < 4; mf++)
                    #pragma unroll
                    for (int nf = 0; nf < 8; nf++)
                        MMA16816(acc[mf][nf], afr[mf], bfr[nf]);
            }
        }
        __syncthreads();
    }

    // ---------------- epilogue (two halves of 64 d-rows, staged via smem) -------
    float* smf = (float*)smem;
    if (mode == 0) {
        const float* P = (br == 0) ? bnq : (br == 1) ? bnk : bnv;
        unsigned short* Sdst = (br == 0) ? g_sq : (br == 1) ? g_sk : g_sv;
        int d_local = tid & 63;
        #pragma unroll
        for (int half = 0; half < 2; half++) {
            __syncthreads();
            if (wm == half) {                      // layout [n 256][m 64 pad 68]
                #pragma unroll
                for (int mf = 0; mf < 4; mf++)
                    #pragma unroll
                    for (int nf = 0; nf < 8; nf++)
                        #pragma unroll
                        for (int hi = 0; hi < 2; hi++)
                            #pragma unroll
                            for (int jr = 0; jr < 2; jr++) {
                                int ml = mf*16 + (lane>>2) + 8*hi;
                                int n  = wn*64 + nf*8 + (lane&3)*2 + jr;
                                smf[n*68 + ml] = acc[mf][nf][hi*2+jr];
                            }
            }
            __syncthreads();
            int d = m0 + half*64 + d_local;
            float g = P[d], be = P[C_+d], mn = P[2*C_+d], va = P[3*C_+d];
            float inv = g / sqrtf(va + 1e-5f);
            float ad  = be - mn*inv;
            #pragma unroll
            for (int it = 0; it < 16; it++) {
                int bnl = (tid>>6) + it*4;
                float v = 0.f;
                #pragma unroll
                for (int t = 0; t < T_; t++) {
                    float y = smf[(t*64 + bnl)*68 + d_local]*inv + ad;
                    v = __fadd_rn(v, __fmul_rn(__fsub_rn(y, v), 0.5f));
                    unsigned short sp = 0;
                    if (v >= 1.f) { sp = 0x3F80; v = 0.f; }
                    size_t j = (size_t)t*BNN + bn0 + bnl;
                    Sdst[j*C_ + d] = sp;
                }
            }
        }
    } else {
        int bn = bn0 + (tid & 63);
        int bidx = bn / N_, n = bn - bidx*N_;
        int tt = tid >> 6;
        #pragma unroll
        for (int half = 0; half < 2; half++) {
            __syncthreads();
            if (wm == half) {                      // layout [m 64][n 256 pad 264]
                #pragma unroll
                for (int mf = 0; mf < 4; mf++)
                    #pragma unroll
                    for (int nf = 0; nf < 8; nf++)
                        #pragma unroll
                        for (int hi = 0; hi < 2; hi++)
                            #pragma unroll
                            for (int jr = 0; jr < 2; jr++) {
                                int ml = mf*16 + (lane>>2) + 8*hi;
                                int nn = wn*64 + nf*8 + (lane&3)*2 + jr;
                                smf[ml*264 + nn] = acc[mf][nf][hi*2+jr];
                            }
            }
            __syncthreads();
            for (int it = 0; it < 64; it++) {
                int d = m0 + half*64 + it;
                float g = bnp[d], be = bnp[C_+d], mn = bnp[2*C_+d], va = bnp[3*C_+d];
                float inv = g / sqrtf(va + 1e-5f);
                float ad  = be - mn*inv;
                float bb  = bias[d];
                size_t oi = (size_t)tt*BCN + (size_t)bidx*CN + (size_t)d*N_ + n;
                out[oi] = (smf[it*264 + tid] + bb)*inv + ad + x[oi];
            }
        }
    }
}

// ---------------- attention: y = q @ (k^T v), exact integer ---------------------
__global__ __launch_bounds__(256) void k_attn()
{
    __shared__ unsigned long long qp[196];
    __shared__ uint32_t km[48][8];
    __shared__ uint32_t vm[48][8];
    __shared__ int kv[48][49];

    int tid = threadIdx.x, warp = tid >> 5, lane = tid & 31;
    int blk = blockIdx.x;
    int h = blk & 7; int tb = blk >> 3; int b = tb & 63; int t = tb >> 6;
    size_t jbase = (size_t)t*BNN + (size_t)b*N_;

    unsigned long long qm = 0, kmask = 0, vmask = 0;
    if (tid < 196) {
        size_t rowoff = (jbase + tid)*C_ + (size_t)h*48;
        const uint4* qr = (const uint4*)(g_sq + rowoff);
        const uint4* kr = (const uint4*)(g_sk + rowoff);
        const uint4* vr = (const uint4*)(g_sv + rowoff);
        #pragma unroll
        for (int q6 = 0; q6 < 6; q6++) {
            uint4 uq = qr[q6], uk = kr[q6], uv = vr[q6];
            uint32_t aq[4] = {uq.x,uq.y,uq.z,uq.w};
            uint32_t ak[4] = {uk.x,uk.y,uk.z,uk.w};
            uint32_t av[4] = {uv.x,uv.y,uv.z,uv.w};
            #pragma unroll
            for (int w = 0; w < 4; w++) {
                int base = q6*8 + w*2;
                if (aq[w] & 0xFFFFu) qm |= 1ull << base;
                if (aq[w] >> 16)     qm |= 1ull << (base+1);
                if (ak[w] & 0xFFFFu) kmask |= 1ull << base;
                if (ak[w] >> 16)     kmask |= 1ull << (base+1);
                if (av[w] & 0xFFFFu) vmask |= 1ull << base;
                if (av[w] >> 16)     vmask |= 1ull << (base+1);
            }
        }
        qp[tid] = qm;
    }
    if (warp < 7) {
        #pragma unroll 4
        for (int c = 0; c < 48; c++) {
            uint32_t kb = __ballot_sync(0xffffffffu, (uint32_t)(kmask >> c) & 1u);
            uint32_t vb = __ballot_sync(0xffffffffu, (uint32_t)(vmask >> c) & 1u);
            if (lane == 0) { km[c][warp] = kb; vm[c][warp] = vb; }
        }
    }
    __syncthreads();

    for (int i = tid; i < 48*48; i += 256) {
        int c = i/48, dd = i - (i/48)*48;
        int s = 0;
        #pragma unroll
        for (int w = 0; w < 7; w++) s += __popc(km[c][w] & vm[dd][w]);
        kv[c][dd] = s;
    }
    __syncthreads();

    if (tid < 196) {
        int y[48];
        #pragma unroll
        for (int dd = 0; dd < 48; dd++) y[dd] = 0;
        unsigned long long m = qp[tid];
        while (m) {
            int c = __ffsll((long long)m) - 1;
            m &= m - 1;
            const int* row = kv[c];
            #pragma unroll
            for (int dd = 0; dd < 48; dd++) y[dd] += row[dd];
        }
        float* ob = g_ya + (jbase + tid)*C_ + (size_t)h*48;
        #pragma unroll
        for (int dd = 0; dd < 48; dd += 4) {
            float4 f;
            f.x = (float)y[dd+0]*0.125f; f.y = (float)y[dd+1]*0.125f;
            f.z = (float)y[dd+2]*0.125f; f.w = (float)y[dd+3]*0.125f;
            *(float4*)(ob + dd) = f;
        }
    }
}

// ---------------- launch --------------------------------------------------------
extern "C" void kernel_launch(void* const* d_in, const int* in_sizes, int n_in,
                              void* d_out, int out_size)
{
    const float* x   = (const float*)d_in[0];
    const float* qw  = (const float*)d_in[1];
    const float* kw  = (const float*)d_in[2];
    const float* vw  = (const float*)d_in[3];
    const float* pw  = (const float*)d_in[4];
    const float* pb  = (const float*)d_in[5];
    const float* qbn = (const float*)d_in[6];
    const float* kbn = (const float*)d_in[7];
    const float* vbn = (const float*)d_in[8];
    const float* pbn = (const float*)d_in[9];
    float* out = (float*)d_out;

    cudaFuncSetAttribute(k_gemm, cudaFuncAttributeMaxDynamicSharedMemorySize, SMEM_DYN);

    k_wsplit<<<(WSZ + 255)/256, 256>>>(qw, kw, vw, pw);
    k_lif_in<<<dim3(7, 12, 64), dim3(32, 8)>>>(x);
    k_gemm<<<dim3(196, 3, 3), 256, SMEM_DYN>>>(0, qbn, kbn, vbn, pbn, pb, x, out);
    k_attn<<<2048, 256>>>();
    k_lif_attn<<<(BNN*C_ + 255)/256, 256>>>();
    k_gemm<<<dim3(196, 3, 1), 256, SMEM_DYN>>>(1, qbn, kbn, vbn, pbn, pb, x, out);
}